// round 3
// baseline (speedup 1.0000x reference)
#include <cuda_runtime.h>
#include <cstdint>
#include <cstddef>

// Problem shape
#define B_DIM 4096
#define IN_DIM 1024
#define H_DIM 1024
#define K_DIM 2048          // IN + H concatenated along K
// Tiling
#define BM 256              // batch rows per CTA
#define BH 32               // h columns per CTA
#define BN 128              // 4 gates * BH
#define BK 32               // K per stage (32 fp32)
#define STAGES 3
#define NITER (K_DIM / BK)  // 64
#define THREADS 256         // 8 warps, 4x2 grid of 64x64 warp tiles

// Shared memory layout
#define APITCH 36                                  // words per row (pad 32->36, conflict-free)
#define A_BYTES (BM * APITCH * 4)                  // 36864
#define B_BYTES (BN * APITCH * 4)                  // 18432
#define STAGE_BYTES (A_BYTES + B_BYTES)            // 55296
#define SMEM_BIAS 64                               // 4*32 floats
#define SMEM_DATA 2048
#define SMEM_TOTAL (SMEM_DATA + STAGES * STAGE_BYTES)  // 167936
// Epilogue gates buffer overlays stage area: 256 x 136 x 4 = 139264 <= 165888
#define GPITCH 136

__device__ __forceinline__ uint32_t smem_u32(const void* p) {
    uint32_t a;
    asm("{ .reg .u64 t; cvta.to.shared.u64 t, %1; cvt.u32.u64 %0, t; }" : "=r"(a) : "l"(p));
    return a;
}
__device__ __forceinline__ void cp16(uint32_t dst, const void* src) {
    asm volatile("cp.async.cg.shared.global [%0], [%1], 16;\n" :: "r"(dst), "l"(src));
}
#define CP_COMMIT() asm volatile("cp.async.commit_group;\n" ::: "memory")
#define CP_WAIT(n)  asm volatile("cp.async.wait_group %0;\n" :: "n"(n) : "memory")

__device__ __forceinline__ void mma_tf32(float* d, const uint32_t* a, const uint32_t* b) {
    asm volatile(
        "mma.sync.aligned.m16n8k8.row.col.f32.tf32.tf32.f32 "
        "{%0, %1, %2, %3}, {%4, %5, %6, %7}, {%8, %9}, {%0, %1, %2, %3};"
        : "+f"(d[0]), "+f"(d[1]), "+f"(d[2]), "+f"(d[3])
        : "r"(a[0]), "r"(a[1]), "r"(a[2]), "r"(a[3]), "r"(b[0]), "r"(b[1]));
}

__device__ __forceinline__ float sigmoidf_fast(float x) {
    return 1.0f / (1.0f + __expf(-x));
}
__device__ __forceinline__ float tanhf_fast(float x) {
    float e = __expf(2.0f * x);
    return (e - 1.0f) / (e + 1.0f);
}

__global__ void __launch_bounds__(THREADS, 1)
lstm_kernel(const float* __restrict__ x, const float* __restrict__ hprev,
            const float* __restrict__ cprev,
            const float* __restrict__ Wxi, const float* __restrict__ Whi, const float* __restrict__ bi,
            const float* __restrict__ Wxf, const float* __restrict__ Whf, const float* __restrict__ bfv,
            const float* __restrict__ Wxg, const float* __restrict__ Whg, const float* __restrict__ bg,
            const float* __restrict__ Wxo, const float* __restrict__ Who, const float* __restrict__ bo,
            float* __restrict__ out_h, float* out_h2, float* out_c)
{
    extern __shared__ char smem[];
    const uint32_t sb = smem_u32(smem);
    const int tid  = threadIdx.x;
    const int lane = tid & 31;
    const int warp = tid >> 5;
    const int g    = lane >> 2;   // group id 0..7
    const int t4   = lane & 3;    // thread-in-group 0..3
    const int wm   = warp >> 1;   // warp m index 0..3 (64-row tiles)
    const int wn   = warp & 1;    // warp n index 0..1 (64-col tiles)

    const int bid   = blockIdx.x;
    const int htile = bid & 31;   // 32 h tiles
    const int mtile = bid >> 5;   // 16 m tiles
    const int m0 = mtile * BM;
    const int h0 = htile * BH;

    // --- bias staging ---
    if (tid < 32) {
        float* bs = (float*)(smem + SMEM_BIAS);
        bs[0 * 32 + tid] = bi[h0 + tid];
        bs[1 * 32 + tid] = bfv[h0 + tid];
        bs[2 * 32 + tid] = bg[h0 + tid];
        bs[3 * 32 + tid] = bo[h0 + tid];
    }

    // --- cp.async descriptors: 8 A chunks + 4 B chunks (16B each) per thread ---
    const float* const Wx[4] = {Wxi, Wxf, Wxg, Wxo};
    const float* const Wh[4] = {Whi, Whf, Whg, Who};

    const float* aptr[8];
    const float* bptr[4];
    uint32_t dA[8], dB[4];
    int brow_g[4], brow_w[4];

    #pragma unroll
    for (int j = 0; j < 8; j++) {
        int id  = tid + THREADS * j;       // 0..2047
        int row = id >> 3;                 // 0..255
        int c   = id & 7;                  // 16B chunk
        aptr[j] = x + (size_t)(m0 + row) * IN_DIM + c * 4;
        dA[j]   = (uint32_t)(row * (APITCH * 4) + c * 16);
    }
    #pragma unroll
    for (int j = 0; j < 4; j++) {
        int id  = tid + THREADS * j;       // 0..1023
        int row = id >> 3;                 // 0..127
        int c   = id & 7;
        int gate = row >> 5;
        int wrow = h0 + (row & 31);
        brow_g[j] = gate; brow_w[j] = wrow;
        bptr[j] = Wx[gate] + (size_t)wrow * IN_DIM + c * 4;
        dB[j]   = (uint32_t)(A_BYTES + row * (APITCH * 4) + c * 16);
    }

    auto issue_stage = [&](int it) {
        if (it == NITER / 2) {  // switch from x/Wx to h/Wh at k=1024
            #pragma unroll
            for (int j = 0; j < 8; j++) {
                int id  = tid + THREADS * j;
                int row = id >> 3;
                int c   = id & 7;
                aptr[j] = hprev + (size_t)(m0 + row) * H_DIM + c * 4;
            }
            #pragma unroll
            for (int j = 0; j < 4; j++) {
                int id = tid + THREADS * j;
                int c  = id & 7;
                bptr[j] = Wh[brow_g[j]] + (size_t)brow_w[j] * H_DIM + c * 4;
            }
        }
        uint32_t sbase = sb + SMEM_DATA + (uint32_t)(it % STAGES) * STAGE_BYTES;
        #pragma unroll
        for (int j = 0; j < 8; j++) { cp16(sbase + dA[j], aptr[j]); aptr[j] += BK; }
        #pragma unroll
        for (int j = 0; j < 4; j++) { cp16(sbase + dB[j], bptr[j]); bptr[j] += BK; }
        CP_COMMIT();
    };

    // --- accumulators: 4 (m) x 8 (n) mma tiles of 16x8 ---
    float acc[4][8][4];
    #pragma unroll
    for (int mi = 0; mi < 4; mi++)
        #pragma unroll
        for (int ni = 0; ni < 8; ni++)
            #pragma unroll
            for (int r = 0; r < 4; r++) acc[mi][ni][r] = 0.0f;

    // --- prologue ---
    issue_stage(0);
    issue_stage(1);

    // --- main loop ---
    for (int tt = 0; tt < NITER; tt++) {
        CP_WAIT(STAGES - 2);     // stage tt resident
        __syncthreads();
        if (tt + STAGES - 1 < NITER) issue_stage(tt + STAGES - 1);

        const int s = tt % STAGES;
        const uint32_t* As = (const uint32_t*)(smem + SMEM_DATA + (size_t)s * STAGE_BYTES);
        const uint32_t* Bs = As + BM * APITCH;

        #pragma unroll
        for (int kt = 0; kt < 4; kt++) {
            const int kc = kt * 8 + t4;
            uint32_t af[4][4], bf[8][2];
            #pragma unroll
            for (int mi = 0; mi < 4; mi++) {
                int r0 = wm * 64 + mi * 16 + g;
                af[mi][0] = As[r0 * APITCH + kc];
                af[mi][1] = As[(r0 + 8) * APITCH + kc];
                af[mi][2] = As[r0 * APITCH + kc + 4];
                af[mi][3] = As[(r0 + 8) * APITCH + kc + 4];
            }
            #pragma unroll
            for (int ni = 0; ni < 8; ni++) {
                int n = wn * 64 + ni * 8 + g;
                bf[ni][0] = Bs[n * APITCH + kc];
                bf[ni][1] = Bs[n * APITCH + kc + 4];
            }
            #pragma unroll
            for (int ni = 0; ni < 8; ni++)
                #pragma unroll
                for (int mi = 0; mi < 4; mi++)
                    mma_tf32(acc[mi][ni], af[mi], bf[ni]);
        }
    }
    CP_WAIT(0);
    __syncthreads();

    // --- epilogue: accums -> smem gates buffer [256][GPITCH] ---
    float* gs = (float*)(smem + SMEM_DATA);
    #pragma unroll
    for (int mi = 0; mi < 4; mi++) {
        #pragma unroll
        for (int ni = 0; ni < 8; ni++) {
            int row = wm * 64 + mi * 16 + g;
            int col = wn * 64 + ni * 8 + 2 * t4;
            *(float2*)(gs + row * GPITCH + col)       = make_float2(acc[mi][ni][0], acc[mi][ni][1]);
            *(float2*)(gs + (row + 8) * GPITCH + col) = make_float2(acc[mi][ni][2], acc[mi][ni][3]);
        }
    }
    __syncthreads();

    // --- pointwise LSTM + writes (float4 over h) ---
    const float* bs = (const float*)(smem + SMEM_BIAS);
    #pragma unroll
    for (int rep = 0; rep < 8; rep++) {
        int idx = tid + THREADS * rep;    // 0..2047
        int m  = idx >> 3;                // 0..255
        int h4 = idx & 7;                 // float4 over 32 h cols
        const float* grow = gs + m * GPITCH;

        float4 zi = *(const float4*)(grow + 0 * 32 + h4 * 4);
        float4 zf = *(const float4*)(grow + 1 * 32 + h4 * 4);
        float4 zg = *(const float4*)(grow + 2 * 32 + h4 * 4);
        float4 zo = *(const float4*)(grow + 3 * 32 + h4 * 4);
        float4 vbi = *(const float4*)(bs + 0 * 32 + h4 * 4);
        float4 vbf = *(const float4*)(bs + 1 * 32 + h4 * 4);
        float4 vbg = *(const float4*)(bs + 2 * 32 + h4 * 4);
        float4 vbo = *(const float4*)(bs + 3 * 32 + h4 * 4);

        size_t go = (size_t)(m0 + m) * H_DIM + h0 + h4 * 4;
        float4 cp = *(const float4*)(cprev + go);

        float hv[4], cv[4];
        float azi[4] = {zi.x, zi.y, zi.z, zi.w};
        float azf[4] = {zf.x, zf.y, zf.z, zf.w};
        float azg[4] = {zg.x, zg.y, zg.z, zg.w};
        float azo[4] = {zo.x, zo.y, zo.z, zo.w};
        float abi[4] = {vbi.x, vbi.y, vbi.z, vbi.w};
        float abf[4] = {vbf.x, vbf.y, vbf.z, vbf.w};
        float abg[4] = {vbg.x, vbg.y, vbg.z, vbg.w};
        float abo[4] = {vbo.x, vbo.y, vbo.z, vbo.w};
        float acp[4] = {cp.x, cp.y, cp.z, cp.w};

        #pragma unroll
        for (int j = 0; j < 4; j++) {
            float ig = sigmoidf_fast(azi[j] + abi[j]);
            float fg = sigmoidf_fast(azf[j] + abf[j]);
            float gg = tanhf_fast(azg[j] + abg[j]);
            float og = sigmoidf_fast(azo[j] + abo[j]);
            cv[j] = fg * acp[j] + ig * gg;
            hv[j] = og * tanhf_fast(cv[j]);
        }
        float4 hv4 = make_float4(hv[0], hv[1], hv[2], hv[3]);
        float4 cv4 = make_float4(cv[0], cv[1], cv[2], cv[3]);
        *(float4*)(out_h + go) = hv4;
        if (out_h2) *(float4*)(out_h2 + go) = hv4;
        if (out_c)  *(float4*)(out_c + go)  = cv4;
    }
}

extern "C" void kernel_launch(void* const* d_in, const int* in_sizes, int n_in,
                              void* d_out, int out_size) {
    const float* x      = (const float*)d_in[0];
    const float* h_prev = (const float*)d_in[1];
    const float* c_prev = (const float*)d_in[2];
    const float* W_ii = (const float*)d_in[3];
    const float* W_hi = (const float*)d_in[4];
    const float* b_i  = (const float*)d_in[5];
    const float* W_if = (const float*)d_in[6];
    const float* W_hf = (const float*)d_in[7];
    const float* b_f  = (const float*)d_in[8];
    const float* W_ig = (const float*)d_in[9];
    const float* W_hg = (const float*)d_in[10];
    const float* b_g  = (const float*)d_in[11];
    const float* W_io = (const float*)d_in[12];
    const float* W_ho = (const float*)d_in[13];
    const float* b_o  = (const float*)d_in[14];

    float* out = (float*)d_out;
    const int HB = B_DIM * H_DIM;   // 4194304
    float* oh  = out;
    float* oh2 = nullptr;
    float* oc  = nullptr;
    if (out_size >= 3 * HB)      { oh2 = out + HB; oc = out + 2 * HB; }
    else if (out_size >= 2 * HB) { oc = out + HB; }

    static bool attr_set = false;
    if (!attr_set) {
        cudaFuncSetAttribute(lstm_kernel, cudaFuncAttributeMaxDynamicSharedMemorySize, SMEM_TOTAL);
        attr_set = true;
    }
    lstm_kernel<<<(B_DIM / BM) * (H_DIM / BH), THREADS, SMEM_TOTAL>>>(
        x, h_prev, c_prev,
        W_ii, W_hi, b_i,
        W_if, W_hf, b_f,
        W_ig, W_hg, b_g,
        W_io, W_ho, b_o,
        oh, oh2, oc);
}

// round 5
// speedup vs baseline: 2.9817x; 2.9817x over previous
#include <cuda_runtime.h>
#include <cuda_fp16.h>
#include <cstdint>
#include <cstddef>

// Problem shape
#define B_DIM 4096
#define IN_DIM 1024
#define H_DIM 1024
#define K_DIM 2048          // IN + H concatenated along K
// Tiling
#define BM 128              // batch rows per CTA
#define BH 64               // h columns per CTA
#define BN 256              // 4 gates * BH
#define BK 64               // K per stage (64 fp16 = 128B row)
#define STAGES 3
#define NITER (K_DIM / BK)  // 32
#define THREADS 512         // 16 warps, 4x4, warp tile 32x64

// fp16 scratch (static device arrays; no allocation)
__device__ __half g_xh[(size_t)B_DIM * K_DIM];   // [4096][2048]  x | h_prev
__device__ __half g_w[(size_t)4 * H_DIM * K_DIM];// [gate*1024+h][2048]  Wx | Wh

// Shared memory layout
#define RPITCH 144                                 // bytes per K-row (128 + 16 pad)
#define PHALF  72                                  // pitch in halves
#define A_BYTES (BM * RPITCH)                      // 18432
#define B_BYTES (BN * RPITCH)                      // 36864
#define STAGE_BYTES (A_BYTES + B_BYTES)            // 55296
#define SMEM_BIAS 64                               // 4*64 floats = 1024B
#define SMEM_DATA 2048
#define SMEM_TOTAL (SMEM_DATA + STAGES * STAGE_BYTES)  // 167936
// Epilogue gates buffer overlays stage area: 128 x 264 x 4 = 135168 <= 165888
#define GPITCH 264

__device__ __forceinline__ uint32_t smem_u32(const void* p) {
    uint32_t a;
    asm("{ .reg .u64 t; cvta.to.shared.u64 t, %1; cvt.u32.u64 %0, t; }" : "=r"(a) : "l"(p));
    return a;
}
__device__ __forceinline__ void cp16(uint32_t dst, const void* src) {
    asm volatile("cp.async.cg.shared.global [%0], [%1], 16;\n" :: "r"(dst), "l"(src));
}
#define CP_COMMIT() asm volatile("cp.async.commit_group;\n" ::: "memory")
#define CP_WAIT(n)  asm volatile("cp.async.wait_group %0;\n" :: "n"(n) : "memory")

__device__ __forceinline__ void mma_f16(float* d, const uint32_t* a, const uint32_t* b) {
    asm volatile(
        "mma.sync.aligned.m16n8k16.row.col.f32.f16.f16.f32 "
        "{%0, %1, %2, %3}, {%4, %5, %6, %7}, {%8, %9}, {%0, %1, %2, %3};"
        : "+f"(d[0]), "+f"(d[1]), "+f"(d[2]), "+f"(d[3])
        : "r"(a[0]), "r"(a[1]), "r"(a[2]), "r"(a[3]), "r"(b[0]), "r"(b[1]));
}

__device__ __forceinline__ float sigmoidf_fast(float x) {
    return 1.0f / (1.0f + __expf(-x));
}
__device__ __forceinline__ float tanhf_fast(float x) {
    float e = __expf(2.0f * x);
    return (e - 1.0f) / (e + 1.0f);
}

// ---------------- conversion kernels ----------------
// 8 halves (two float4 reads -> one uint4 write) per thread.

__global__ void __launch_bounds__(256)
conv_xh_kernel(const float* __restrict__ x, const float* __restrict__ h) {
    size_t i = (size_t)blockIdx.x * blockDim.x + threadIdx.x;   // 0 .. 1M-1
    size_t e = i * 8;
    int row = (int)(e >> 11);
    int k   = (int)(e & 2047);
    const float* src = (k < IN_DIM) ? (x + (size_t)row * IN_DIM + k)
                                    : (h + (size_t)row * H_DIM + (k - IN_DIM));
    float4 v0 = *(const float4*)(src);
    float4 v1 = *(const float4*)(src + 4);
    __half2 h0 = __floats2half2_rn(v0.x, v0.y);
    __half2 h1 = __floats2half2_rn(v0.z, v0.w);
    __half2 h2 = __floats2half2_rn(v1.x, v1.y);
    __half2 h3 = __floats2half2_rn(v1.z, v1.w);
    uint4 o;
    o.x = *(uint32_t*)&h0; o.y = *(uint32_t*)&h1;
    o.z = *(uint32_t*)&h2; o.w = *(uint32_t*)&h3;
    *(uint4*)(g_xh + e) = o;
}

__global__ void __launch_bounds__(256)
conv_w_kernel(const float* __restrict__ Wxi, const float* __restrict__ Whi,
              const float* __restrict__ Wxf, const float* __restrict__ Whf,
              const float* __restrict__ Wxg, const float* __restrict__ Whg,
              const float* __restrict__ Wxo, const float* __restrict__ Who) {
    const float* const Wx[4] = {Wxi, Wxf, Wxg, Wxo};
    const float* const Wh[4] = {Whi, Whf, Whg, Who};
    size_t i = (size_t)blockIdx.x * blockDim.x + threadIdx.x;
    size_t e = i * 8;
    int row  = (int)(e >> 11);          // gate*1024 + h
    int k    = (int)(e & 2047);
    int gate = row >> 10;
    int hh   = row & 1023;
    const float* src = (k < IN_DIM) ? (Wx[gate] + (size_t)hh * IN_DIM + k)
                                    : (Wh[gate] + (size_t)hh * H_DIM + (k - IN_DIM));
    float4 v0 = *(const float4*)(src);
    float4 v1 = *(const float4*)(src + 4);
    __half2 h0 = __floats2half2_rn(v0.x, v0.y);
    __half2 h1 = __floats2half2_rn(v0.z, v0.w);
    __half2 h2 = __floats2half2_rn(v1.x, v1.y);
    __half2 h3 = __floats2half2_rn(v1.z, v1.w);
    uint4 o;
    o.x = *(uint32_t*)&h0; o.y = *(uint32_t*)&h1;
    o.z = *(uint32_t*)&h2; o.w = *(uint32_t*)&h3;
    *(uint4*)(g_w + e) = o;
}

// ---------------- main fused GEMM + LSTM kernel ----------------

__global__ void __launch_bounds__(THREADS, 1)
lstm_kernel(const float* __restrict__ cprev,
            const float* __restrict__ bi, const float* __restrict__ bfv,
            const float* __restrict__ bg, const float* __restrict__ bo,
            float* __restrict__ out_h, float* out_h2, float* out_c)
{
    extern __shared__ char smem[];
    const uint32_t sb = smem_u32(smem);
    const int tid  = threadIdx.x;
    const int lane = tid & 31;
    const int warp = tid >> 5;
    const int g    = lane >> 2;   // 0..7
    const int t4   = lane & 3;    // 0..3
    const int wm   = warp >> 2;   // 0..3  (32-row tiles)
    const int wn   = warp & 3;    // 0..3  (64-col tiles)

    const int bid   = blockIdx.x;
    const int htile = bid & 15;   // 16 h tiles
    const int mtile = bid >> 4;   // 32 m tiles
    const int m0 = mtile * BM;
    const int h0 = htile * BH;

    // --- bias staging ---
    if (tid < 64) {
        float* bs = (float*)(smem + SMEM_BIAS);
        bs[0 * 64 + tid] = bi[h0 + tid];
        bs[1 * 64 + tid] = bfv[h0 + tid];
        bs[2 * 64 + tid] = bg[h0 + tid];
        bs[3 * 64 + tid] = bo[h0 + tid];
    }

    // --- cp.async descriptors: A 2 chunks + B 4 chunks (16B) per thread ---
    const __half* aptr[2];
    const __half* bptr[4];
    uint32_t dA[2], dB[4];

    #pragma unroll
    for (int j = 0; j < 2; j++) {
        int id  = tid + THREADS * j;       // 0..1023
        int row = id >> 3;                 // 0..127
        int c   = id & 7;                  // 16B chunk (8 halves)
        aptr[j] = g_xh + (size_t)(m0 + row) * K_DIM + c * 8;
        dA[j]   = (uint32_t)(row * RPITCH + c * 16);
    }
    #pragma unroll
    for (int j = 0; j < 4; j++) {
        int id  = tid + THREADS * j;       // 0..2047
        int row = id >> 3;                 // 0..255
        int c   = id & 7;
        int gate = row >> 6;
        int wrow = gate * H_DIM + h0 + (row & 63);
        bptr[j] = g_w + (size_t)wrow * K_DIM + c * 8;
        dB[j]   = (uint32_t)(A_BYTES + row * RPITCH + c * 16);
    }

    auto issue_stage = [&](int it) {
        uint32_t sbase = sb + SMEM_DATA + (uint32_t)(it % STAGES) * STAGE_BYTES;
        #pragma unroll
        for (int j = 0; j < 2; j++) { cp16(sbase + dA[j], aptr[j]); aptr[j] += BK; }
        #pragma unroll
        for (int j = 0; j < 4; j++) { cp16(sbase + dB[j], bptr[j]); bptr[j] += BK; }
        CP_COMMIT();
    };

    // --- accumulators: 2 (m) x 8 (n) tiles of 16x8 ---
    float acc[2][8][4];
    #pragma unroll
    for (int mi = 0; mi < 2; mi++)
        #pragma unroll
        for (int ni = 0; ni < 8; ni++)
            #pragma unroll
            for (int r = 0; r < 4; r++) acc[mi][ni][r] = 0.0f;

    // --- prologue ---
    issue_stage(0);
    issue_stage(1);

    // --- main loop ---
    for (int tt = 0; tt < NITER; tt++) {
        CP_WAIT(STAGES - 2);
        __syncthreads();
        if (tt + STAGES - 1 < NITER) issue_stage(tt + STAGES - 1);

        const int s = tt % STAGES;
        const __half* As = (const __half*)(smem + SMEM_DATA + (size_t)s * STAGE_BYTES);
        const __half* Bs = (const __half*)(smem + SMEM_DATA + (size_t)s * STAGE_BYTES + A_BYTES);

        #pragma unroll
        for (int kt = 0; kt < 4; kt++) {           // 4 x k16 per 64-K stage
            const int kc = kt * 16 + 2 * t4;       // half index
            uint32_t af[2][4], bf[8][2];
            #pragma unroll
            for (int mi = 0; mi < 2; mi++) {
                int r0 = wm * 32 + mi * 16 + g;
                af[mi][0] = *(const uint32_t*)&As[r0 * PHALF + kc];
                af[mi][1] = *(const uint32_t*)&As[(r0 + 8) * PHALF + kc];
                af[mi][2] = *(const uint32_t*)&As[r0 * PHALF + kc + 8];
                af[mi][3] = *(const uint32_t*)&As[(r0 + 8) * PHALF + kc + 8];
            }
            #pragma unroll
            for (int ni = 0; ni < 8; ni++) {
                int n = wn * 64 + ni * 8 + g;
                bf[ni][0] = *(const uint32_t*)&Bs[n * PHALF + kc];
                bf[ni][1] = *(const uint32_t*)&Bs[n * PHALF + kc + 8];
            }
            #pragma unroll
            for (int ni = 0; ni < 8; ni++)
                #pragma unroll
                for (int mi = 0; mi < 2; mi++)
                    mma_f16(acc[mi][ni], af[mi], bf[ni]);
        }
    }
    CP_WAIT(0);
    __syncthreads();

    // --- epilogue: accums -> smem gates buffer [128][GPITCH] ---
    float* gs = (float*)(smem + SMEM_DATA);
    #pragma unroll
    for (int mi = 0; mi < 2; mi++) {
        #pragma unroll
        for (int ni = 0; ni < 8; ni++) {
            int row = wm * 32 + mi * 16 + g;
            int col = wn * 64 + ni * 8 + 2 * t4;
            *(float2*)(gs + row * GPITCH + col)       = make_float2(acc[mi][ni][0], acc[mi][ni][1]);
            *(float2*)(gs + (row + 8) * GPITCH + col) = make_float2(acc[mi][ni][2], acc[mi][ni][3]);
        }
    }
    __syncthreads();

    // --- pointwise LSTM + writes (float4 over 64 h cols) ---
    const float* bs = (const float*)(smem + SMEM_BIAS);
    #pragma unroll
    for (int rep = 0; rep < 4; rep++) {
        int idx = tid + THREADS * rep;    // 0..2047
        int m  = idx >> 4;                // 0..127
        int h4 = idx & 15;                // float4 over 64 h cols
        const float* grow = gs + m * GPITCH;

        float4 zi = *(const float4*)(grow + 0 * 64 + h4 * 4);
        float4 zf = *(const float4*)(grow + 1 * 64 + h4 * 4);
        float4 zg = *(const float4*)(grow + 2 * 64 + h4 * 4);
        float4 zo = *(const float4*)(grow + 3 * 64 + h4 * 4);
        float4 vbi = *(const float4*)(bs + 0 * 64 + h4 * 4);
        float4 vbf = *(const float4*)(bs + 1 * 64 + h4 * 4);
        float4 vbg = *(const float4*)(bs + 2 * 64 + h4 * 4);
        float4 vbo = *(const float4*)(bs + 3 * 64 + h4 * 4);

        size_t go = (size_t)(m0 + m) * H_DIM + h0 + h4 * 4;
        float4 cp = *(const float4*)(cprev + go);

        float hv[4], cv[4];
        float azi[4] = {zi.x, zi.y, zi.z, zi.w};
        float azf[4] = {zf.x, zf.y, zf.z, zf.w};
        float azg[4] = {zg.x, zg.y, zg.z, zg.w};
        float azo[4] = {zo.x, zo.y, zo.z, zo.w};
        float abi[4] = {vbi.x, vbi.y, vbi.z, vbi.w};
        float abf[4] = {vbf.x, vbf.y, vbf.z, vbf.w};
        float abg[4] = {vbg.x, vbg.y, vbg.z, vbg.w};
        float abo[4] = {vbo.x, vbo.y, vbo.z, vbo.w};
        float acp[4] = {cp.x, cp.y, cp.z, cp.w};

        #pragma unroll
        for (int j = 0; j < 4; j++) {
            float ig = sigmoidf_fast(azi[j] + abi[j]);
            float fg = sigmoidf_fast(azf[j] + abf[j]);
            float gg = tanhf_fast(azg[j] + abg[j]);
            float og = sigmoidf_fast(azo[j] + abo[j]);
            cv[j] = fg * acp[j] + ig * gg;
            hv[j] = og * tanhf_fast(cv[j]);
        }
        float4 hv4 = make_float4(hv[0], hv[1], hv[2], hv[3]);
        float4 cv4 = make_float4(cv[0], cv[1], cv[2], cv[3]);
        *(float4*)(out_h + go) = hv4;
        if (out_h2) *(float4*)(out_h2 + go) = hv4;
        if (out_c)  *(float4*)(out_c + go)  = cv4;
    }
}

extern "C" void kernel_launch(void* const* d_in, const int* in_sizes, int n_in,
                              void* d_out, int out_size) {
    const float* x      = (const float*)d_in[0];
    const float* h_prev = (const float*)d_in[1];
    const float* c_prev = (const float*)d_in[2];
    const float* W_ii = (const float*)d_in[3];
    const float* W_hi = (const float*)d_in[4];
    const float* b_i  = (const float*)d_in[5];
    const float* W_if = (const float*)d_in[6];
    const float* W_hf = (const float*)d_in[7];
    const float* b_f  = (const float*)d_in[8];
    const float* W_ig = (const float*)d_in[9];
    const float* W_hg = (const float*)d_in[10];
    const float* b_g  = (const float*)d_in[11];
    const float* W_io = (const float*)d_in[12];
    const float* W_ho = (const float*)d_in[13];
    const float* b_o  = (const float*)d_in[14];

    float* out = (float*)d_out;
    const int HB = B_DIM * H_DIM;   // 4194304
    float* oh  = out;
    float* oh2 = nullptr;
    float* oc  = nullptr;
    if (out_size >= 3 * HB)      { oh2 = out + HB; oc = out + 2 * HB; }
    else if (out_size >= 2 * HB) { oc = out + HB; }

    static bool attr_set = false;
    if (!attr_set) {
        cudaFuncSetAttribute(lstm_kernel, cudaFuncAttributeMaxDynamicSharedMemorySize, SMEM_TOTAL);
        attr_set = true;
    }

    // fp16 conversion pre-passes (each thread packs 8 halves)
    {
        int n8 = (B_DIM * K_DIM) / 8;     // 1,048,576
        conv_xh_kernel<<<n8 / 256, 256>>>(x, h_prev);
        conv_w_kernel<<<n8 / 256, 256>>>(W_ii, W_hi, W_if, W_hf, W_ig, W_hg, W_io, W_ho);
    }

    lstm_kernel<<<(B_DIM / BM) * (H_DIM / BH), THREADS, SMEM_TOTAL>>>(
        c_prev, b_i, b_f, b_g, b_o, oh, oh2, oc);
}

// round 6
// speedup vs baseline: 3.7260x; 1.2496x over previous
#include <cuda_runtime.h>
#include <cuda_fp16.h>
#include <cstdint>
#include <cstddef>

// Problem shape
#define B_DIM 4096
#define IN_DIM 1024
#define H_DIM 1024
#define K_DIM 2048          // IN + H concatenated along K
// Tiling
#define BM 128              // batch rows per CTA
#define BH 64               // h columns per CTA
#define BN 256              // 4 gates * BH
#define BK 64               // K per stage (64 fp16 = 128B row)
#define STAGES 4
#define NITER (K_DIM / BK)  // 32
#define THREADS 512         // 16 warps, 4x4, warp tile 32x64

// fp16 scratch (static device arrays; no allocation)
__device__ __half g_xh[(size_t)B_DIM * K_DIM];    // [4096][2048]  x | h_prev
__device__ __half g_w[(size_t)4 * H_DIM * K_DIM]; // [gate*1024+h][2048]  Wx | Wh

// Shared memory layout: XOR-swizzled 128B rows, no padding
#define A_BYTES (BM * 128)                         // 16384
#define B_BYTES (BN * 128)                         // 32768
#define STAGE_BYTES (A_BYTES + B_BYTES)            // 49152
#define SMEM_BIAS 64                               // 4*64 floats = 1024B
#define SMEM_DATA 2048
#define SMEM_TOTAL (SMEM_DATA + STAGES * STAGE_BYTES)  // 198656
// Epilogue gates buffer overlays stage area: 128 x 264 x 4 = 135168 <= 196608
#define GPITCH 264

__device__ __forceinline__ uint32_t smem_u32(const void* p) {
    uint32_t a;
    asm("{ .reg .u64 t; cvta.to.shared.u64 t, %1; cvt.u32.u64 %0, t; }" : "=r"(a) : "l"(p));
    return a;
}
__device__ __forceinline__ void cp16(uint32_t dst, const void* src) {
    asm volatile("cp.async.cg.shared.global [%0], [%1], 16;\n" :: "r"(dst), "l"(src));
}
#define CP_COMMIT() asm volatile("cp.async.commit_group;\n" ::: "memory")
#define CP_WAIT(n)  asm volatile("cp.async.wait_group %0;\n" :: "n"(n) : "memory")

__device__ __forceinline__ void ldsm4(uint32_t* r, uint32_t addr) {
    asm volatile("ldmatrix.sync.aligned.m8n8.x4.shared.b16 {%0,%1,%2,%3}, [%4];"
                 : "=r"(r[0]), "=r"(r[1]), "=r"(r[2]), "=r"(r[3]) : "r"(addr));
}

__device__ __forceinline__ void mma_f16(float* d, const uint32_t* a, const uint32_t* b) {
    asm volatile(
        "mma.sync.aligned.m16n8k16.row.col.f32.f16.f16.f32 "
        "{%0, %1, %2, %3}, {%4, %5, %6, %7}, {%8, %9}, {%0, %1, %2, %3};"
        : "+f"(d[0]), "+f"(d[1]), "+f"(d[2]), "+f"(d[3])
        : "r"(a[0]), "r"(a[1]), "r"(a[2]), "r"(a[3]), "r"(b[0]), "r"(b[1]));
}

__device__ __forceinline__ float sigmoidf_fast(float x) {
    return 1.0f / (1.0f + __expf(-x));
}
__device__ __forceinline__ float tanhf_fast(float x) {
    float e = __expf(2.0f * x);
    return (e - 1.0f) / (e + 1.0f);
}

// ---------------- merged conversion kernel ----------------
// First half of grid: x|h_prev -> g_xh ; second half: weights -> g_w.
__global__ void __launch_bounds__(256)
conv_kernel(const float* __restrict__ x, const float* __restrict__ h,
            const float* __restrict__ Wxi, const float* __restrict__ Whi,
            const float* __restrict__ Wxf, const float* __restrict__ Whf,
            const float* __restrict__ Wxg, const float* __restrict__ Whg,
            const float* __restrict__ Wxo, const float* __restrict__ Who) {
    const int half = gridDim.x >> 1;
    size_t i = (size_t)(blockIdx.x % half) * blockDim.x + threadIdx.x;  // 0 .. 1M-1
    size_t e = i * 8;
    int row = (int)(e >> 11);
    int k   = (int)(e & 2047);
    const float* src;
    __half* dst;
    if (blockIdx.x < half) {
        src = (k < IN_DIM) ? (x + (size_t)row * IN_DIM + k)
                           : (h + (size_t)row * H_DIM + (k - IN_DIM));
        dst = g_xh + e;
    } else {
        const float* const Wx[4] = {Wxi, Wxf, Wxg, Wxo};
        const float* const Wh[4] = {Whi, Whf, Whg, Who};
        int gate = row >> 10;
        int hh   = row & 1023;
        src = (k < IN_DIM) ? (Wx[gate] + (size_t)hh * IN_DIM + k)
                           : (Wh[gate] + (size_t)hh * H_DIM + (k - IN_DIM));
        dst = g_w + e;
    }
    float4 v0 = *(const float4*)(src);
    float4 v1 = *(const float4*)(src + 4);
    __half2 h0 = __floats2half2_rn(v0.x, v0.y);
    __half2 h1 = __floats2half2_rn(v0.z, v0.w);
    __half2 h2 = __floats2half2_rn(v1.x, v1.y);
    __half2 h3 = __floats2half2_rn(v1.z, v1.w);
    uint4 o;
    o.x = *(uint32_t*)&h0; o.y = *(uint32_t*)&h1;
    o.z = *(uint32_t*)&h2; o.w = *(uint32_t*)&h3;
    *(uint4*)dst = o;
}

// ---------------- main fused GEMM + LSTM kernel ----------------

__global__ void __launch_bounds__(THREADS, 1)
lstm_kernel(const float* __restrict__ cprev,
            const float* __restrict__ bi, const float* __restrict__ bfv,
            const float* __restrict__ bg, const float* __restrict__ bo,
            float* __restrict__ out_h, float* out_h2, float* out_c)
{
    extern __shared__ char smem[];
    const uint32_t sb = smem_u32(smem);
    const int tid  = threadIdx.x;
    const int lane = tid & 31;
    const int warp = tid >> 5;
    const int wm   = warp >> 2;   // 0..3  (32-row tiles)
    const int wn   = warp & 3;    // 0..3  (64-col tiles)

    const int bid   = blockIdx.x;
    const int htile = bid & 15;   // 16 h tiles
    const int mtile = bid >> 4;   // 32 m tiles
    const int m0 = mtile * BM;
    const int h0 = htile * BH;

    // --- bias staging ---
    if (tid < 64) {
        float* bs = (float*)(smem + SMEM_BIAS);
        bs[0 * 64 + tid] = bi[h0 + tid];
        bs[1 * 64 + tid] = bfv[h0 + tid];
        bs[2 * 64 + tid] = bg[h0 + tid];
        bs[3 * 64 + tid] = bo[h0 + tid];
    }

    // --- cp.async descriptors (XOR swizzle: chunk ^= row&7) ---
    const __half* aptr[2];
    const __half* bptr[4];
    uint32_t dA[2], dB[4];

    #pragma unroll
    for (int j = 0; j < 2; j++) {
        int id  = tid + THREADS * j;       // 0..1023
        int row = id >> 3;                 // 0..127
        int c   = id & 7;                  // 16B chunk (8 halves)
        aptr[j] = g_xh + (size_t)(m0 + row) * K_DIM + c * 8;
        dA[j]   = (uint32_t)(row * 128 + ((c ^ (row & 7)) << 4));
    }
    #pragma unroll
    for (int j = 0; j < 4; j++) {
        int id  = tid + THREADS * j;       // 0..2047
        int row = id >> 3;                 // 0..255
        int c   = id & 7;
        int gate = row >> 6;
        int wrow = gate * H_DIM + h0 + (row & 63);
        bptr[j] = g_w + (size_t)wrow * K_DIM + c * 8;
        dB[j]   = (uint32_t)(A_BYTES + row * 128 + ((c ^ (row & 7)) << 4));
    }

    auto issue_stage = [&](int it) {
        uint32_t sbase = sb + SMEM_DATA + (uint32_t)(it % STAGES) * STAGE_BYTES;
        #pragma unroll
        for (int j = 0; j < 2; j++) { cp16(sbase + dA[j], aptr[j]); aptr[j] += BK; }
        #pragma unroll
        for (int j = 0; j < 4; j++) { cp16(sbase + dB[j], bptr[j]); bptr[j] += BK; }
        CP_COMMIT();
    };

    // --- ldmatrix per-lane geometry ---
    const int q   = lane >> 3;      // 0..3
    const int qlo = q & 1;
    const int qhi = q >> 1;
    const int lr  = lane & 7;

    // A frag mi: matrix rows = wm*32 + mi*16 + qlo*8 + lr, chunk = kt*2 + qhi
    uint32_t aoff[2];
    #pragma unroll
    for (int mi = 0; mi < 2; mi++) {
        int rowA = wm * 32 + mi * 16 + qlo * 8 + lr;
        aoff[mi] = (uint32_t)(rowA * 128);
    }
    const uint32_t axor = (uint32_t)((wm * 32 + qlo * 8 + lr) & 7);

    // B pair p (n8 tiles 2p,2p+1): rows = wn*64 + p*16 + qhi*8 + lr, chunk = kt*2 + qlo
    uint32_t boff[4];
    #pragma unroll
    for (int p = 0; p < 4; p++) {
        int rowB = wn * 64 + p * 16 + qhi * 8 + lr;
        boff[p] = (uint32_t)(A_BYTES + rowB * 128);
    }
    const uint32_t bxor = (uint32_t)((wn * 64 + qhi * 8 + lr) & 7);

    // --- accumulators: 2 (m) x 8 (n) tiles of 16x8 ---
    float acc[2][8][4];
    #pragma unroll
    for (int mi = 0; mi < 2; mi++)
        #pragma unroll
        for (int ni = 0; ni < 8; ni++)
            #pragma unroll
            for (int r = 0; r < 4; r++) acc[mi][ni][r] = 0.0f;

    // --- prologue: fill STAGES-1 stages ---
    #pragma unroll
    for (int s = 0; s < STAGES - 1; s++) issue_stage(s);

    // --- main loop ---
    for (int tt = 0; tt < NITER; tt++) {
        CP_WAIT(STAGES - 2);
        __syncthreads();
        if (tt + STAGES - 1 < NITER) issue_stage(tt + STAGES - 1);

        const uint32_t sbase = sb + SMEM_DATA + (uint32_t)(tt % STAGES) * STAGE_BYTES;

        #pragma unroll
        for (int kt = 0; kt < 4; kt++) {           // 4 x k16 per 64-K stage
            uint32_t af[2][4], bf[8][2];
            const uint32_t ca = (uint32_t)(kt * 2) + (uint32_t)qhi;
            #pragma unroll
            for (int mi = 0; mi < 2; mi++)
                ldsm4(af[mi], sbase + aoff[mi] + (((ca ^ axor)) << 4));
            const uint32_t cb = (uint32_t)(kt * 2) + (uint32_t)qlo;
            #pragma unroll
            for (int p = 0; p < 4; p++) {
                uint32_t r[4];
                ldsm4(r, sbase + boff[p] + (((cb ^ bxor)) << 4));
                bf[2 * p][0]     = r[0];
                bf[2 * p][1]     = r[1];
                bf[2 * p + 1][0] = r[2];
                bf[2 * p + 1][1] = r[3];
            }
            #pragma unroll
            for (int ni = 0; ni < 8; ni++)
                #pragma unroll
                for (int mi = 0; mi < 2; mi++)
                    mma_f16(acc[mi][ni], af[mi], bf[ni]);
        }
    }
    CP_WAIT(0);
    __syncthreads();

    // --- epilogue: accums -> smem gates buffer [128][GPITCH] ---
    const int g  = lane >> 2;
    const int t4 = lane & 3;
    float* gs = (float*)(smem + SMEM_DATA);
    #pragma unroll
    for (int mi = 0; mi < 2; mi++) {
        #pragma unroll
        for (int ni = 0; ni < 8; ni++) {
            int row = wm * 32 + mi * 16 + g;
            int col = wn * 64 + ni * 8 + 2 * t4;
            *(float2*)(gs + row * GPITCH + col)       = make_float2(acc[mi][ni][0], acc[mi][ni][1]);
            *(float2*)(gs + (row + 8) * GPITCH + col) = make_float2(acc[mi][ni][2], acc[mi][ni][3]);
        }
    }
    __syncthreads();

    // --- pointwise LSTM + writes (float4 over 64 h cols) ---
    const float* bs = (const float*)(smem + SMEM_BIAS);
    #pragma unroll
    for (int rep = 0; rep < 4; rep++) {
        int idx = tid + THREADS * rep;    // 0..2047
        int m  = idx >> 4;                // 0..127
        int h4 = idx & 15;                // float4 over 64 h cols
        const float* grow = gs + m * GPITCH;

        float4 zi = *(const float4*)(grow + 0 * 64 + h4 * 4);
        float4 zf = *(const float4*)(grow + 1 * 64 + h4 * 4);
        float4 zg = *(const float4*)(grow + 2 * 64 + h4 * 4);
        float4 zo = *(const float4*)(grow + 3 * 64 + h4 * 4);
        float4 vbi = *(const float4*)(bs + 0 * 64 + h4 * 4);
        float4 vbf = *(const float4*)(bs + 1 * 64 + h4 * 4);
        float4 vbg = *(const float4*)(bs + 2 * 64 + h4 * 4);
        float4 vbo = *(const float4*)(bs + 3 * 64 + h4 * 4);

        size_t go = (size_t)(m0 + m) * H_DIM + h0 + h4 * 4;
        float4 cp = *(const float4*)(cprev + go);

        float hv[4], cv[4];
        float azi[4] = {zi.x, zi.y, zi.z, zi.w};
        float azf[4] = {zf.x, zf.y, zf.z, zf.w};
        float azg[4] = {zg.x, zg.y, zg.z, zg.w};
        float azo[4] = {zo.x, zo.y, zo.z, zo.w};
        float abi[4] = {vbi.x, vbi.y, vbi.z, vbi.w};
        float abf[4] = {vbf.x, vbf.y, vbf.z, vbf.w};
        float abg[4] = {vbg.x, vbg.y, vbg.z, vbg.w};
        float abo[4] = {vbo.x, vbo.y, vbo.z, vbo.w};
        float acp[4] = {cp.x, cp.y, cp.z, cp.w};

        #pragma unroll
        for (int j = 0; j < 4; j++) {
            float ig = sigmoidf_fast(azi[j] + abi[j]);
            float fg = sigmoidf_fast(azf[j] + abf[j]);
            float gg = tanhf_fast(azg[j] + abg[j]);
            float og = sigmoidf_fast(azo[j] + abo[j]);
            cv[j] = fg * acp[j] + ig * gg;
            hv[j] = og * tanhf_fast(cv[j]);
        }
        float4 hv4 = make_float4(hv[0], hv[1], hv[2], hv[3]);
        float4 cv4 = make_float4(cv[0], cv[1], cv[2], cv[3]);
        *(float4*)(out_h + go) = hv4;
        if (out_h2) *(float4*)(out_h2 + go) = hv4;
        if (out_c)  *(float4*)(out_c + go)  = cv4;
    }
}

extern "C" void kernel_launch(void* const* d_in, const int* in_sizes, int n_in,
                              void* d_out, int out_size) {
    const float* x      = (const float*)d_in[0];
    const float* h_prev = (const float*)d_in[1];
    const float* c_prev = (const float*)d_in[2];
    const float* W_ii = (const float*)d_in[3];
    const float* W_hi = (const float*)d_in[4];
    const float* b_i  = (const float*)d_in[5];
    const float* W_if = (const float*)d_in[6];
    const float* W_hf = (const float*)d_in[7];
    const float* b_f  = (const float*)d_in[8];
    const float* W_ig = (const float*)d_in[9];
    const float* W_hg = (const float*)d_in[10];
    const float* b_g  = (const float*)d_in[11];
    const float* W_io = (const float*)d_in[12];
    const float* W_ho = (const float*)d_in[13];
    const float* b_o  = (const float*)d_in[14];

    float* out = (float*)d_out;
    const int HB = B_DIM * H_DIM;   // 4194304
    float* oh  = out;
    float* oh2 = nullptr;
    float* oc  = nullptr;
    if (out_size >= 3 * HB)      { oh2 = out + HB; oc = out + 2 * HB; }
    else if (out_size >= 2 * HB) { oc = out + HB; }

    static bool attr_set = false;
    if (!attr_set) {
        cudaFuncSetAttribute(lstm_kernel, cudaFuncAttributeMaxDynamicSharedMemorySize, SMEM_TOTAL);
        attr_set = true;
    }

    // fp16 conversion pre-pass (merged: first half xh, second half weights)
    {
        int n8 = (B_DIM * K_DIM) / 8;     // 1,048,576 chunks per half
        conv_kernel<<<2 * (n8 / 256), 256>>>(x, h_prev,
                                             W_ii, W_hi, W_if, W_hf,
                                             W_ig, W_hg, W_io, W_ho);
    }

    lstm_kernel<<<(B_DIM / BM) * (H_DIM / BH), THREADS, SMEM_TOTAL>>>(
        c_prev, b_i, b_f, b_g, b_o, oh, oh2, oc);
}